// round 6
// baseline (speedup 1.0000x reference)
#include <cuda_runtime.h>
#include <math.h>

// EGNN layer collapsed to the diagonal. Per row r:
//   t1 = silu(h@(We1a+We1b) + sqrt(EPS)*We1[2F] + be1)
//   t2 = silu(t1@We2 + be2)
//   att = sigmoid(t2.Wa + ba)                 [warp-uniform scalar]
//   t3 = silu(bn1 + h@Wn1a + att*(t2@Wn1b))   [att factored out]
//   out = t3@Wn2 + bn2
// Latency-bound: keep R4 shape (2 rows/warp, 1024 warps = ~1.7/SMSP) but
// serve all weights from SHARED MEMORY (cooperative float4 fill, We1 folded
// at fill time). LDS (29cyc, pipelined) replaces per-warp LDG streams and
// the 64-entry register arrays -> shorter per-warp critical path, regs ~80.

#define SQRT_EPS 0.0031622776601683794f  // sqrt(1e-5)
#define FULL 0xffffffffu

__device__ __forceinline__ float silu_f(float v) {
    return __fdividef(v, 1.0f + __expf(-v));
}
__device__ __forceinline__ float sigmoid_f(float v) {
    return __fdividef(1.0f, 1.0f + __expf(-v));
}

__global__ void __launch_bounds__(128, 1)
egnn_diag_kernel(const float* __restrict__ h,
                 const float* __restrict__ x,
                 const float* __restrict__ We1, const float* __restrict__ be1,
                 const float* __restrict__ We2, const float* __restrict__ be2,
                 const float* __restrict__ Wa,  const float* __restrict__ ba,
                 const float* __restrict__ Wn1, const float* __restrict__ bn1,
                 const float* __restrict__ Wn2, const float* __restrict__ bn2,
                 float* __restrict__ out, float* __restrict__ xout, int R)
{
    // [f][lane] layout, conflict-free LDS (lane = bank)
    __shared__ float s_w1 [1024];   // We1[0:F] + We1[F:2F] folded
    __shared__ float s_wna[1024];   // Wn1[0:F]
    __shared__ float s_wnb[1024];   // Wn1[F:2F]
    __shared__ float s_we2[1024];
    __shared__ float s_wn2[1024];

    const int tid  = threadIdx.x;
    const int lane = tid & 31;

    // ---- cooperative smem fill (float4: 256 vec4 per matrix, 128 threads) ----
    {
        const float4* We1v = (const float4*)We1;
        const float4* Wn1v = (const float4*)Wn1;
        const float4* We2v = (const float4*)We2;
        const float4* Wn2v = (const float4*)Wn2;
        #pragma unroll
        for (int i = tid; i < 256; i += 128) {
            float4 a = We1v[i];
            float4 b = We1v[256 + i];
            ((float4*)s_w1)[i] = make_float4(a.x + b.x, a.y + b.y, a.z + b.z, a.w + b.w);
            ((float4*)s_wna)[i] = Wn1v[i];
            ((float4*)s_wnb)[i] = Wn1v[256 + i];
            ((float4*)s_we2)[i] = We2v[i];
            ((float4*)s_wn2)[i] = Wn2v[i];
        }
    }

    const int warp = (blockIdx.x * blockDim.x + tid) >> 5;
    const int r0 = warp * 2;
    const int r1 = r0 + 1;
    const bool has0 = (r0 < R);
    const bool has1 = (r1 < R);

    // ---- independent per-warp front work (overlaps the smem fill) ----
    const float hv0 = has0 ? h[r0 * 32 + lane] : 0.f;
    const float hv1 = has1 ? h[r1 * 32 + lane] : 0.f;

    if (lane < 6 && r0 * 3 + lane < R * 3)       // 6 floats = x rows r0,r1
        xout[r0 * 3 + lane] = x[r0 * 3 + lane];

    const float b1  = be1[lane] + SQRT_EPS * We1[64 * 32 + lane];
    const float b2  = be2[lane];
    const float wa  = Wa[lane];
    const float ba0 = ba[0];
    const float b3  = bn1[lane];
    const float b4  = bn2[lane];

    __syncthreads();

    // ---- layer 1 + S_h fused (one shfl pair feeds We1-fold and Wn1a) ----
    float a0_0 = b1, a1_0 = 0.f, a0_1 = b1, a1_1 = 0.f;
    float sh0a = 0.f, sh0b = 0.f, sh1a = 0.f, sh1b = 0.f;
    #pragma unroll
    for (int f = 0; f < 32; f += 2) {
        const float w1a = s_w1 [(f + 0) * 32 + lane];
        const float wna = s_wna[(f + 0) * 32 + lane];
        const float hf0a = __shfl_sync(FULL, hv0, f + 0);
        const float hf1a = __shfl_sync(FULL, hv1, f + 0);
        a0_0 += hf0a * w1a;  a0_1 += hf1a * w1a;
        sh0a += hf0a * wna;  sh1a += hf1a * wna;

        const float w1b = s_w1 [(f + 1) * 32 + lane];
        const float wnb = s_wna[(f + 1) * 32 + lane];
        const float hf0b = __shfl_sync(FULL, hv0, f + 1);
        const float hf1b = __shfl_sync(FULL, hv1, f + 1);
        a1_0 += hf0b * w1b;  a1_1 += hf1b * w1b;
        sh0b += hf0b * wnb;  sh1b += hf1b * wnb;
    }
    const float t1_0 = silu_f(a0_0 + a1_0);
    const float t1_1 = silu_f(a0_1 + a1_1);
    const float sh0 = sh0a + sh0b;
    const float sh1 = sh1a + sh1b;

    // ---- layer 2: t2 = silu(t1 @ We2 + be2) ----
    a0_0 = b2; a1_0 = 0.f; a0_1 = b2; a1_1 = 0.f;
    #pragma unroll
    for (int f = 0; f < 32; f += 2) {
        const float wa2 = s_we2[(f + 0) * 32 + lane];
        const float wb2 = s_we2[(f + 1) * 32 + lane];
        a0_0 += __shfl_sync(FULL, t1_0, f + 0) * wa2;
        a0_1 += __shfl_sync(FULL, t1_1, f + 0) * wa2;
        a1_0 += __shfl_sync(FULL, t1_0, f + 1) * wb2;
        a1_1 += __shfl_sync(FULL, t1_1, f + 1) * wb2;
    }
    const float t2_0 = silu_f(a0_0 + a1_0);
    const float t2_1 = silu_f(a0_1 + a1_1);

    // ---- att butterfly overlapped with S_t2 = t2 @ Wn1b ----
    float s0 = t2_0 * wa;
    float s1 = t2_1 * wa;
    float st0a = 0.f, st0b = 0.f, st1a = 0.f, st1b = 0.f;
    #pragma unroll
    for (int f = 0; f < 32; f += 2) {
        const float wba = s_wnb[(f + 0) * 32 + lane];
        const float wbb = s_wnb[(f + 1) * 32 + lane];
        st0a += __shfl_sync(FULL, t2_0, f + 0) * wba;
        st1a += __shfl_sync(FULL, t2_1, f + 0) * wba;
        st0b += __shfl_sync(FULL, t2_0, f + 1) * wbb;
        st1b += __shfl_sync(FULL, t2_1, f + 1) * wbb;
    }
    #pragma unroll
    for (int off = 16; off > 0; off >>= 1) {
        s0 += __shfl_xor_sync(FULL, s0, off);
        s1 += __shfl_xor_sync(FULL, s1, off);
    }
    const float att0 = sigmoid_f(s0 + ba0);
    const float att1 = sigmoid_f(s1 + ba0);

    // ---- layer 3 epilogue: t3 = silu(b3 + S_h + att * S_t2) ----
    const float t3_0 = silu_f(b3 + sh0 + att0 * (st0a + st0b));
    const float t3_1 = silu_f(b3 + sh1 + att1 * (st1a + st1b));

    // ---- layer 4: out = t3 @ Wn2 + bn2 ----
    a0_0 = b4; a1_0 = 0.f; a0_1 = b4; a1_1 = 0.f;
    #pragma unroll
    for (int f = 0; f < 32; f += 2) {
        const float wa4 = s_wn2[(f + 0) * 32 + lane];
        const float wb4 = s_wn2[(f + 1) * 32 + lane];
        a0_0 += __shfl_sync(FULL, t3_0, f + 0) * wa4;
        a0_1 += __shfl_sync(FULL, t3_1, f + 0) * wa4;
        a1_0 += __shfl_sync(FULL, t3_0, f + 1) * wb4;
        a1_1 += __shfl_sync(FULL, t3_1, f + 1) * wb4;
    }

    if (has0) out[r0 * 32 + lane] = a0_0 + a1_0;
    if (has1) out[r1 * 32 + lane] = a0_1 + a1_1;
}

extern "C" void kernel_launch(void* const* d_in, const int* in_sizes, int n_in,
                              void* d_out, int out_size)
{
    const float* h   = (const float*)d_in[0];
    const float* x   = (const float*)d_in[1];
    const float* We1 = (const float*)d_in[2];
    const float* be1 = (const float*)d_in[3];
    const float* We2 = (const float*)d_in[4];
    const float* be2 = (const float*)d_in[5];
    const float* Wa  = (const float*)d_in[6];
    const float* ba  = (const float*)d_in[7];
    const float* Wn1 = (const float*)d_in[8];
    const float* bn1 = (const float*)d_in[9];
    const float* Wn2 = (const float*)d_in[10];
    const float* bn2 = (const float*)d_in[11];

    const int R = in_sizes[0] / 32;          // B*N rows
    float* out  = (float*)d_out;             // [R, 32]
    float* xout = out + (size_t)R * 32;      // [R, 3] passthrough

    const int nwarps  = (R + 1) / 2;         // 2 rows/warp -> 1024 warps
    const int threads = 128;                 // 4 warps/block -> 256 blocks
    const int blocks  = (nwarps * 32 + threads - 1) / threads;
    egnn_diag_kernel<<<blocks, threads>>>(h, x, We1, be1, We2, be2, Wa, ba,
                                          Wn1, bn1, Wn2, bn2, out, xout, R);
}